// round 14
// baseline (speedup 1.0000x reference)
#include <cuda_runtime.h>
#include <cuda_bf16.h>
#include <cstdint>
#include <math.h>

// Problem constants (fixed by the reference setup_inputs)
#define BB 256   // batches
#define AA 64    // atoms
#define EE 128   // edges
#define KK 6     // neighbors
#define HH 256   // hidden

#define NTHREADS 256
#define WPC 8                       // warps per CTA = edges per CTA
#define NCTAS (BB * EE / WPC)       // 4096 CTAs
#define R4 (HH / 4)                 // 64 float4 per rep row

// Force-issued non-coherent 128-bit load: volatile asm keeps program order
// among these loads, so all 12 gather loads issue before any FMA consumes.
__device__ __forceinline__ float4 ldg128(const float4* p) {
    float4 v;
    asm volatile("ld.global.nc.v4.f32 {%0,%1,%2,%3}, [%4];"
                 : "=f"(v.x), "=f"(v.y), "=f"(v.z), "=f"(v.w) : "l"(p));
    return v;
}

__global__ __launch_bounds__(NTHREADS)
void DirectedEdgeMessage_89885075571226_kernel(
    const float* __restrict__ rep,     // [B, E, H]
    const int*   __restrict__ pairs,   // [B, E, 2]
    const int*   __restrict__ nbrs,    // [B, E, K]
    const float* __restrict__ xyz,     // [B, A, 3]
    float*       __restrict__ out)     // [B, E, H]
{
    const int wid = threadIdx.x >> 5;
    const int lid = threadIdx.x & 31;
    const int b   = blockIdx.x >> 4;                  // 16 CTAs per batch
    const int e   = ((blockIdx.x & 15) << 3) + wid;   // this warp's edge

    // ---- lanes 0..5: resolve (neighbor index, distance weight) ----
    int   nk = 0;
    float w  = 0.0f;
    if (lid < KK) {
        nk = __ldg(&nbrs[(b * EE + e) * KK + lid]);
        const int2 pr = __ldg((const int2*)&pairs[(b * EE + nk) * 2]);
        const float* x0 = xyz + (b * AA + pr.x) * 3;
        const float* x1 = xyz + (b * AA + pr.y) * 3;
        const float dx = __ldg(x0 + 0) - __ldg(x1 + 0);
        const float dy = __ldg(x0 + 1) - __ldg(x1 + 1);
        const float dz = __ldg(x0 + 2) - __ldg(x1 + 2);
        const float d2 = dx * dx + dy * dy + dz * dz;
        const float inv = 1.0f / d2;
        w = isinf(inv) ? 0.0f : inv;
    }

    // ---- broadcast 6 packed (row-offset, weight) pairs: 6 shuffles ----
    const unsigned long long packed =
        ((unsigned long long)(unsigned)__float_as_int(w) << 32) |
        (unsigned)(nk * R4);
    const unsigned long long q0 = __shfl_sync(0xFFFFFFFFu, packed, 0);
    const unsigned long long q1 = __shfl_sync(0xFFFFFFFFu, packed, 1);
    const unsigned long long q2 = __shfl_sync(0xFFFFFFFFu, packed, 2);
    const unsigned long long q3 = __shfl_sync(0xFFFFFFFFu, packed, 3);
    const unsigned long long q4 = __shfl_sync(0xFFFFFFFFu, packed, 4);
    const unsigned long long q5 = __shfl_sync(0xFFFFFFFFu, packed, 5);

    const int r0 = (int)(unsigned)q0, r1 = (int)(unsigned)q1;
    const int r2 = (int)(unsigned)q2, r3 = (int)(unsigned)q3;
    const int r4 = (int)(unsigned)q4, r5 = (int)(unsigned)q5;
    const float w0 = __int_as_float((int)(q0 >> 32));
    const float w1 = __int_as_float((int)(q1 >> 32));
    const float w2 = __int_as_float((int)(q2 >> 32));
    const float w3 = __int_as_float((int)(q3 >> 32));
    const float w4 = __int_as_float((int)(q4 >> 32));
    const float w5 = __int_as_float((int)(q5 >> 32));

    // ---- gather: 12 force-issued independent LDG.128 per lane ----
    const float4* __restrict__ rep4 = (const float4*)rep + (size_t)b * (EE * R4);
    const int c0 = lid;         // float4 column 0..31
    const int c1 = lid + 32;    // float4 column 32..63

    const float4 a0 = ldg128(&rep4[r0 + c0]);
    const float4 b0 = ldg128(&rep4[r0 + c1]);
    const float4 a1 = ldg128(&rep4[r1 + c0]);
    const float4 b1 = ldg128(&rep4[r1 + c1]);
    const float4 a2 = ldg128(&rep4[r2 + c0]);
    const float4 b2 = ldg128(&rep4[r2 + c1]);
    const float4 a3 = ldg128(&rep4[r3 + c0]);
    const float4 b3 = ldg128(&rep4[r3 + c1]);
    const float4 a4 = ldg128(&rep4[r4 + c0]);
    const float4 b4 = ldg128(&rep4[r4 + c1]);
    const float4 a5 = ldg128(&rep4[r5 + c0]);
    const float4 b5 = ldg128(&rep4[r5 + c1]);

    // ---- flat FMA trees (two independent accumulator pairs) ----
    float4 accA, accB, tA, tB;
    accA.x = w0 * a0.x; accA.y = w0 * a0.y; accA.z = w0 * a0.z; accA.w = w0 * a0.w;
    accB.x = w0 * b0.x; accB.y = w0 * b0.y; accB.z = w0 * b0.z; accB.w = w0 * b0.w;
    tA.x   = w1 * a1.x; tA.y   = w1 * a1.y; tA.z   = w1 * a1.z; tA.w   = w1 * a1.w;
    tB.x   = w1 * b1.x; tB.y   = w1 * b1.y; tB.z   = w1 * b1.z; tB.w   = w1 * b1.w;

    accA.x = fmaf(w2, a2.x, accA.x); accA.y = fmaf(w2, a2.y, accA.y);
    accA.z = fmaf(w2, a2.z, accA.z); accA.w = fmaf(w2, a2.w, accA.w);
    accB.x = fmaf(w2, b2.x, accB.x); accB.y = fmaf(w2, b2.y, accB.y);
    accB.z = fmaf(w2, b2.z, accB.z); accB.w = fmaf(w2, b2.w, accB.w);
    tA.x   = fmaf(w3, a3.x, tA.x);   tA.y   = fmaf(w3, a3.y, tA.y);
    tA.z   = fmaf(w3, a3.z, tA.z);   tA.w   = fmaf(w3, a3.w, tA.w);
    tB.x   = fmaf(w3, b3.x, tB.x);   tB.y   = fmaf(w3, b3.y, tB.y);
    tB.z   = fmaf(w3, b3.z, tB.z);   tB.w   = fmaf(w3, b3.w, tB.w);

    accA.x = fmaf(w4, a4.x, accA.x); accA.y = fmaf(w4, a4.y, accA.y);
    accA.z = fmaf(w4, a4.z, accA.z); accA.w = fmaf(w4, a4.w, accA.w);
    accB.x = fmaf(w4, b4.x, accB.x); accB.y = fmaf(w4, b4.y, accB.y);
    accB.z = fmaf(w4, b4.z, accB.z); accB.w = fmaf(w4, b4.w, accB.w);
    tA.x   = fmaf(w5, a5.x, tA.x);   tA.y   = fmaf(w5, a5.y, tA.y);
    tA.z   = fmaf(w5, a5.z, tA.z);   tA.w   = fmaf(w5, a5.w, tA.w);
    tB.x   = fmaf(w5, b5.x, tB.x);   tB.y   = fmaf(w5, b5.y, tB.y);
    tB.z   = fmaf(w5, b5.z, tB.z);   tB.w   = fmaf(w5, b5.w, tB.w);

    accA.x += tA.x; accA.y += tA.y; accA.z += tA.z; accA.w += tA.w;
    accB.x += tB.x; accB.y += tB.y; accB.z += tB.z; accB.w += tB.w;

    // ---- store this edge's H row (fully coalesced) ----
    float4* __restrict__ out4 = (float4*)out + ((size_t)b * EE + e) * R4;
    out4[c0] = accA;
    out4[c1] = accB;
}

extern "C" void kernel_launch(void* const* d_in, const int* in_sizes, int n_in,
                              void* d_out, int out_size)
{
    const float* rep   = (const float*)d_in[0];  // bond_representations [1,B,E,H]
    const int*   pairs = (const int*)  d_in[1];  // bond_pairs [B,E,2]
    const int*   nbrs  = (const int*)  d_in[2];  // bond_neighbors [B,E,K]
    const float* xyz   = (const float*)d_in[3];  // xyz [B,A,3]
    float*       out   = (float*)d_out;          // [1,B,E,H]

    DirectedEdgeMessage_89885075571226_kernel<<<NCTAS, NTHREADS>>>(
        rep, pairs, nbrs, xyz, out);
}